// round 3
// baseline (speedup 1.0000x reference)
#include <cuda_runtime.h>
#include <cuda_bf16.h>
#include <cstdint>

// SpatiallyJitterColorChannels: per-(b,c) 2D roll of x[64,3,512,512] fp32.
// out[b,c,h,w] = x[b,c,(h-sh)&511,(w-sw)&511], sh/sw = shifts[b,c,:]-2, |s|<=2.
//
// R3 strategy: single aligned LDG.128 per output quad + warp shuffle.
//  - Thread t's neighbor quad B_t == A_{t+1} (lanes contiguous in w on the
//    same source row; row crossings only at warp boundaries). Get it via
//    __shfl_down_sync(A,1); only lane 31 loads its neighbor explicitly.
//    => read requests per warp drop from 64 to 33 LDG.128.
//  - .cs (evict-first) hints on both streams: 2x192MB >> L2, pure streaming.
//  - o = select offset in {0..3}, uniform per plane (blocks never straddle
//    planes); o==0 path skips shuffles entirely.

#define SHIFT 2

__global__ void __launch_bounds__(256) roll2d_kernel(
    const float* __restrict__ x,
    const int*   __restrict__ shifts,   // [B, C, 2] int32 in [0, 2*SHIFT]
    float*       __restrict__ out)
{
    int base  = blockIdx.x * 512 + threadIdx.x;   // float4 index of element 0
    int plane = base >> 16;                       // / 65536 f4 per plane
    int lane  = threadIdx.x & 31;

    int sh = shifts[plane * 2 + 0] - SHIFT;
    int sw = shifts[plane * 2 + 1] - SHIFT;

    int qa_off = (sw > 0) ? -4 : 0;
    int o      = (sw > 0) ? 4 - sw : -sw;         // select offset, 0..3

    const float* planep = x + ((size_t)plane << 18);   // * 262144
    float4* out4 = reinterpret_cast<float4*>(out);

    float4       A[2];
    const float* rowp[2];
    int          qa[2], oidx[2];

    #pragma unroll
    for (int e = 0; e < 2; e++) {
        int idx    = base + e * 256;
        int within = idx & 65535;
        int h      = within >> 7;            // 128 f4 per row
        int w0     = (within & 127) << 2;
        int hs     = (h - sh) & 511;
        rowp[e] = planep + (hs << 9);
        qa[e]   = (w0 + qa_off) & 511;       // aligned quad start
        A[e]    = __ldcs(reinterpret_cast<const float4*>(rowp[e] + qa[e]));
        oidx[e] = idx;
    }

    if (o == 0) {                            // sw == 0: pure row-roll copy
        #pragma unroll
        for (int e = 0; e < 2; e++)
            __stcs(out4 + oidx[e], A[e]);
        return;
    }

    // Lane 31 has no in-warp neighbor: load its B quad explicitly.
    float4 X[2];
    if (lane == 31) {
        #pragma unroll
        for (int e = 0; e < 2; e++)
            X[e] = __ldcs(reinterpret_cast<const float4*>(
                              rowp[e] + ((qa[e] + 4) & 511)));
    }

    #pragma unroll
    for (int e = 0; e < 2; e++) {
        float4 N;
        N.x = __shfl_down_sync(0xffffffffu, A[e].x, 1);
        N.y = __shfl_down_sync(0xffffffffu, A[e].y, 1);
        N.z = __shfl_down_sync(0xffffffffu, A[e].z, 1);
        N.w = __shfl_down_sync(0xffffffffu, A[e].w, 1);
        if (lane == 31) N = X[e];

        float4 v;
        switch (o) {   // uniform per plane -> no divergence
            case 1:  v = make_float4(A[e].y, A[e].z, A[e].w, N.x); break;
            case 2:  v = make_float4(A[e].z, A[e].w, N.x, N.y);    break;
            default: v = make_float4(A[e].w, N.x, N.y, N.z);       break;
        }
        __stcs(out4 + oidx[e], v);
    }
}

extern "C" void kernel_launch(void* const* d_in, const int* in_sizes, int n_in,
                              void* d_out, int out_size)
{
    const float* x      = (const float*)d_in[0];
    const int*   shifts = (const int*)d_in[1];
    float*       out    = (float*)d_out;

    int n_f4   = out_size / 4;               // 12582912
    int blocks = n_f4 / 512;                 // 24576
    roll2d_kernel<<<blocks, 256>>>(x, shifts, out);
}